// round 3
// baseline (speedup 1.0000x reference)
#include <cuda_runtime.h>
#include <cuda_bf16.h>
#include <cstdint>
#include <cstddef>

#define N_PTS 8192
#define DIMS  128
#define KNBR  14

// ---------------- scratch (__device__ globals: the sanctioned no-alloc workaround) -------------
__device__ __align__(16) __nv_bfloat16 g_XB[N_PTS * DIMS];          // 2 MB bf16 copy of X
__device__ float  g_SQ[N_PTS];                                      // fp32 row norms |x_i|^2
__device__ __align__(16) float g_SKEY[67108864];                    // 256 MB: key[i][j] = s_ij - 0.5*sq_j
__device__ int    g_NBR[N_PTS * KNBR];                              // top-14 neighbor indices per row
__device__ double g_partial_bulk[512];
__device__ double g_partial_corr[1024];

// ---------------- fast-math helpers (1 MUFU each) ----------------
__device__ __forceinline__ float f_sqrt(float x){ float r; asm("sqrt.approx.f32 %0, %1;" : "=f"(r) : "f"(x)); return r; }
__device__ __forceinline__ float f_rcp (float x){ float r; asm("rcp.approx.f32 %0, %1;"  : "=f"(r) : "f"(x)); return r; }
__device__ __forceinline__ float f_lg2 (float x){ float r; asm("lg2.approx.f32 %0, %1;"  : "=f"(r) : "f"(x)); return r; }
__device__ __forceinline__ float f_ex2 (float x){ float r; asm("ex2.approx.f32 %0, %1;"  : "=f"(r) : "f"(x)); return r; }

#define LN2F 0.69314718055994531f
#define LOG2EF 1.4426950408889634f

// ---------------- 1) prep: bf16 convert + row norms (warp per row) ----------------
__global__ void prep_kernel(const float* __restrict__ X) {
    int warp = threadIdx.x >> 5, lane = threadIdx.x & 31;
    int row  = blockIdx.x * 8 + warp;
    const float* xr = X + (size_t)row * DIMS;
    float v0 = xr[lane], v1 = xr[lane + 32], v2 = xr[lane + 64], v3 = xr[lane + 96];
    __nv_bfloat16* xb = g_XB + (size_t)row * DIMS;
    xb[lane]      = __float2bfloat16(v0);
    xb[lane + 32] = __float2bfloat16(v1);
    xb[lane + 64] = __float2bfloat16(v2);
    xb[lane + 96] = __float2bfloat16(v3);
    float s = v0*v0 + v1*v1 + v2*v2 + v3*v3;
    #pragma unroll
    for (int off = 16; off; off >>= 1) s += __shfl_xor_sync(0xffffffffu, s, off);
    if (lane == 0) g_SQ[row] = s;
}

// ---------------- 2) GEMM (bf16 HMMA) -> key matrix ----------------
__device__ __forceinline__ void mma16816(float* c, const uint32_t* a, const uint32_t* b) {
    asm volatile(
        "mma.sync.aligned.m16n8k16.row.col.f32.bf16.bf16.f32 "
        "{%0,%1,%2,%3}, {%4,%5,%6,%7}, {%8,%9}, {%0,%1,%2,%3};"
        : "+f"(c[0]), "+f"(c[1]), "+f"(c[2]), "+f"(c[3])
        : "r"(a[0]), "r"(a[1]), "r"(a[2]), "r"(a[3]), "r"(b[0]), "r"(b[1]));
}

#define SM_STRIDE 136   // 128 + 8 bf16 pad -> conflict-free 32-bit LDS

__global__ __launch_bounds__(256, 2) void gemm_key_kernel() {
    extern __shared__ __align__(16) char smem_raw[];
    __nv_bfloat16* sA = (__nv_bfloat16*)smem_raw;
    __nv_bfloat16* sB = sA + 128 * SM_STRIDE;
    float* sSQ = (float*)(sB + 128 * SM_STRIDE);

    int tid = threadIdx.x;
    int rowBlk = blockIdx.y * 128, colBlk = blockIdx.x * 128;

    #pragma unroll
    for (int i = 0; i < 8; i++) {
        int idx = tid + i * 256;
        int r = idx >> 4, q = idx & 15;
        *(uint4*)(sA + r * SM_STRIDE + q * 8) = *(const uint4*)(g_XB + (size_t)(rowBlk + r) * DIMS + q * 8);
        *(uint4*)(sB + r * SM_STRIDE + q * 8) = *(const uint4*)(g_XB + (size_t)(colBlk + r) * DIMS + q * 8);
    }
    if (tid < 128) sSQ[tid] = g_SQ[colBlk + tid];
    __syncthreads();

    int warp = tid >> 5, lane = tid & 31;
    int wm = warp & 3, wn = warp >> 2;      // 4x2 warp grid: 32x64 per warp
    int grp = lane >> 2, tig = lane & 3;

    float acc[2][8][4];
    #pragma unroll
    for (int mt = 0; mt < 2; mt++)
        #pragma unroll
        for (int nt = 0; nt < 8; nt++)
            #pragma unroll
            for (int q = 0; q < 4; q++) acc[mt][nt][q] = 0.f;

    const __nv_bfloat16* pA = sA + (wm * 32) * SM_STRIDE;
    const __nv_bfloat16* pB = sB + (wn * 64) * SM_STRIDE;

    #pragma unroll
    for (int kk = 0; kk < 8; kk++) {
        int kb = kk * 16;
        uint32_t afr[2][4];
        #pragma unroll
        for (int mt = 0; mt < 2; mt++) {
            const __nv_bfloat16* base = pA + (mt * 16 + grp) * SM_STRIDE + kb + tig * 2;
            afr[mt][0] = *(const uint32_t*)(base);
            afr[mt][1] = *(const uint32_t*)(base + 8 * SM_STRIDE);
            afr[mt][2] = *(const uint32_t*)(base + 8);
            afr[mt][3] = *(const uint32_t*)(base + 8 * SM_STRIDE + 8);
        }
        uint32_t bfr[8][2];
        #pragma unroll
        for (int nt = 0; nt < 8; nt++) {
            const __nv_bfloat16* base = pB + (nt * 8 + grp) * SM_STRIDE + kb + tig * 2;
            bfr[nt][0] = *(const uint32_t*)(base);
            bfr[nt][1] = *(const uint32_t*)(base + 8);
        }
        #pragma unroll
        for (int mt = 0; mt < 2; mt++)
            #pragma unroll
            for (int nt = 0; nt < 8; nt++)
                mma16816(acc[mt][nt], afr[mt], bfr[nt]);
    }

    // epilogue: key = s_ij - 0.5*sq_j  (rank-equivalent to -d^2 per row)
    #pragma unroll
    for (int mt = 0; mt < 2; mt++) {
        #pragma unroll
        for (int nt = 0; nt < 8; nt++) {
            int lr = wm * 32 + mt * 16 + grp;
            int lc = wn * 64 + nt * 8 + tig * 2;
            float h0 = 0.5f * sSQ[lc], h1 = 0.5f * sSQ[lc + 1];
            size_t base = (size_t)(rowBlk + lr) * N_PTS + colBlk + lc;
            float2 v0 = make_float2(acc[mt][nt][0] - h0, acc[mt][nt][1] - h1);
            *(float2*)(g_SKEY + base) = v0;
            float2 v1 = make_float2(acc[mt][nt][2] - h0, acc[mt][nt][3] - h1);
            *(float2*)(g_SKEY + base + (size_t)8 * N_PTS) = v1;
        }
    }
}

// ---------------- 3) top-14 per row (warp per row) ----------------
__global__ void topk_kernel() {
    __shared__ float skey[8][32 * KNBR];
    __shared__ int   sidx[8][32 * KNBR];
    int warp = threadIdx.x >> 5, lane = threadIdx.x & 31;
    int row  = blockIdx.x * 8 + warp;
    const float4* prow = (const float4*)(g_SKEY + (size_t)row * N_PTS);

    float bk[KNBR]; int bi[KNBR];
    #pragma unroll
    for (int s = 0; s < KNBR; s++) { bk[s] = -3.4e38f; bi[s] = -1; }

    auto tryins = [&](float v, int j) {
        if (v > bk[KNBR - 1]) {
            float cv = v; int ci = j;
            #pragma unroll
            for (int s = 0; s < KNBR; s++) {
                if (cv > bk[s]) {
                    float tf = bk[s]; bk[s] = cv; cv = tf;
                    int   ti = bi[s]; bi[s] = ci; ci = ti;
                }
            }
        }
    };

    for (int t = 0; t < N_PTS / 128; t++) {
        int jq = t * 32 + lane;          // coalesced float4 reads
        float4 v = prow[jq];
        int j = jq * 4;
        tryins(v.x, j); tryins(v.y, j + 1); tryins(v.z, j + 2); tryins(v.w, j + 3);
    }

    #pragma unroll
    for (int s = 0; s < KNBR; s++) { skey[warp][lane * KNBR + s] = bk[s]; sidx[warp][lane * KNBR + s] = bi[s]; }
    __syncwarp();

    int p = 0;
    for (int r = 0; r < KNBR; r++) {
        float cand = (p < KNBR) ? skey[warp][lane * KNBR + p] : -3.4e38f;
        int   cidx = (p < KNBR) ? sidx[warp][lane * KNBR + p] : 0x7fffffff;
        int   owner = lane;
        #pragma unroll
        for (int off = 16; off; off >>= 1) {   // total order (key desc, idx asc) -> all lanes converge
            float ov = __shfl_xor_sync(0xffffffffu, cand, off);
            int   oi = __shfl_xor_sync(0xffffffffu, cidx, off);
            int   ow = __shfl_xor_sync(0xffffffffu, owner, off);
            if (ov > cand || (ov == cand && oi < cidx)) { cand = ov; cidx = oi; owner = ow; }
        }
        if (lane == owner) p++;
        if (lane == 0) g_NBR[row * KNBR + r] = cidx;
    }
}

// ---------------- 4) bulk lo-dim loss: sum over ALL pairs of ln(1 - lo_sim + eps) ----------------
__global__ void bulk_kernel(const float* __restrict__ LO) {
    __shared__ float2 sLo[512];
    __shared__ double sred[256];
    int tid = threadIdx.x;
    const float2* lo2 = (const float2*)LO;
    float2 me = lo2[blockIdx.x * 256 + tid];
    int j0 = blockIdx.y * 512;
    sLo[tid]       = lo2[j0 + tid];
    sLo[tid + 256] = lo2[j0 + 256 + tid];
    __syncthreads();

    float accf = 0.f;
    #pragma unroll 4
    for (int j = 0; j < 512; j++) {
        float2 o = sLo[j];
        float dx = me.x - o.x, dy = me.y - o.y;
        float d2 = fmaf(dx, dx, dy * dy);
        float d  = f_sqrt(d2);
        float r  = f_rcp(1.0f + d);
        float t  = (1.0f - r) + 1e-10f;
        accf += f_lg2(t);
    }
    sred[tid] = (double)(accf * LN2F);
    __syncthreads();
    for (int off = 128; off; off >>= 1) { if (tid < off) sred[tid] += sred[tid + off]; __syncthreads(); }
    if (tid == 0) g_partial_bulk[blockIdx.y * 32 + blockIdx.x] = sred[0];
}

// ---------------- 5) exact neighbor correction (warp per row) ----------------
// adds: hi_sim*ln(lo_sim+eps) - ln(1-lo_sim+eps)  for each of the 14 neighbors
__global__ void corr_kernel(const float* __restrict__ X, const float* __restrict__ LO) {
    __shared__ double wsum[8];
    int warp = threadIdx.x >> 5, lane = threadIdx.x & 31;
    int row  = blockIdx.x * 8 + warp;
    const float* xi = X + (size_t)row * DIMS;
    float a0 = xi[lane], a1 = xi[lane + 32], a2 = xi[lane + 64], a3 = xi[lane + 96];
    const float2* lo2 = (const float2*)LO;
    float2 li = lo2[row];
    float sqi = g_SQ[row];

    float acc = 0.f;
    for (int n = 0; n < KNBR; n++) {
        int j = g_NBR[row * KNBR + n];
        const float* xj = X + (size_t)j * DIMS;
        float dot = a0 * xj[lane] + a1 * xj[lane + 32] + a2 * xj[lane + 64] + a3 * xj[lane + 96];
        #pragma unroll
        for (int off = 16; off; off >>= 1) dot += __shfl_xor_sync(0xffffffffu, dot, off);
        float d2h = sqi + g_SQ[j] - 2.f * dot;
        d2h = fmaxf(d2h, 0.f);
        float hd = f_sqrt(d2h);
        float hs = f_ex2(-LOG2EF * hd);          // exp(-hi_d)
        float2 lj = lo2[j];
        float dx = li.x - lj.x, dy = li.y - lj.y;
        float ld = f_sqrt(fmaf(dx, dx, dy * dy));
        float r  = f_rcp(1.0f + ld);
        float A  = hs * (f_lg2(r + 1e-10f) * LN2F);
        float Bs = f_lg2((1.0f - r) + 1e-10f) * LN2F;   // same expression the bulk kernel added
        acc += (A - Bs);
    }
    if (lane == 0) wsum[warp] = (double)acc;
    __syncthreads();
    if (threadIdx.x == 0) {
        double s = 0;
        for (int k = 0; k < 8; k++) s += wsum[k];
        g_partial_corr[blockIdx.x] = s;
    }
}

// ---------------- 6) deterministic final reduce ----------------
__global__ void final_kernel(float* __restrict__ out) {
    __shared__ double sred[256];
    int t = threadIdx.x;
    double s = 0;
    for (int k = t; k < 512;  k += 256) s += g_partial_bulk[k];
    for (int k = t; k < 1024; k += 256) s += g_partial_corr[k];
    sred[t] = s;
    __syncthreads();
    for (int off = 128; off; off >>= 1) { if (t < off) sred[t] += sred[t + off]; __syncthreads(); }
    if (t == 0) out[0] = (float)(-(sred[0] / 67108864.0) * 100.0);
}

// ---------------- launch ----------------
extern "C" void kernel_launch(void* const* d_in, const int* in_sizes, int n_in,
                              void* d_out, int out_size) {
    const float* X; const float* LO;
    if (in_sizes[0] == N_PTS * DIMS) { X = (const float*)d_in[0]; LO = (const float*)d_in[1]; }
    else                             { X = (const float*)d_in[1]; LO = (const float*)d_in[0]; }

    int smem_gemm = 2 * 128 * SM_STRIDE * 2 + 128 * 4;   // 70144 B
    cudaFuncSetAttribute(gemm_key_kernel, cudaFuncAttributeMaxDynamicSharedMemorySize, smem_gemm);

    prep_kernel    <<<N_PTS / 8, 256>>>(X);
    gemm_key_kernel<<<dim3(N_PTS / 128, N_PTS / 128), 256, smem_gemm>>>();
    topk_kernel    <<<N_PTS / 8, 256>>>();
    bulk_kernel    <<<dim3(32, 16), 256>>>(LO);
    corr_kernel    <<<N_PTS / 8, 256>>>(X, LO);
    final_kernel   <<<1, 256>>>((float*)d_out);
}